// round 13
// baseline (speedup 1.0000x reference)
#include <cuda_runtime.h>
#include <cuda_fp16.h>
#include <cstdint>

#define Bsz 128
#define Edim 1024
#define Hdim 512
#define Vocab 32000
#define Steps 30
#define NG 2048
#define TOKCOLS 31
#define LOGB (Bsz*TOKCOLS)
#define SWZ128(o) ((o) ^ (((o) >> 3) & 0x70))
#define LOSCALE 2048.0f
#define INVLOSCALE (1.0f/2048.0f)

typedef unsigned long long u64;

__device__ __align__(16) float g_X[Bsz*Edim];
__device__ __align__(16) float g_emb[Bsz*Hdim];
__device__ __align__(16) float g_h0[Bsz*Hdim];
__device__ __align__(16) float g_c0[Bsz*Hdim];
__device__ __align__(16) float g_h1[Bsz*Hdim];
__device__ __align__(16) float g_c1[Bsz*Hdim];
__device__ __align__(16) float g_part[4][Bsz*NG];
__device__ u64 g_samp[Bsz];
__device__ __align__(16) __half g_WTh[(size_t)Vocab*Hdim];
__device__ __align__(16) __half g_WTl[(size_t)Vocab*Hdim];   // lo * 2048
__device__ __align__(16) __half g_h1h[Bsz*Hdim], g_h1l[Bsz*Hdim];  // lo * 2048

__device__ __forceinline__ void split_sc(float x, __half* h, __half* l) {
    __half hh = __float2half_rn(x);
    *h = hh;
    *l = __float2half_rn((x - __half2float(hh)) * LOSCALE);
}

// ------------------------- threefry (partitionable) --------------------------
__device__ __forceinline__ uint32_t rotl32(uint32_t x, int r) {
    return __funnelshift_l(x, x, r);
}

__device__ __forceinline__ uint32_t threefry_xored(uint32_t k0, uint32_t k1, uint32_t j) {
    uint32_t ks2 = k0 ^ k1 ^ 0x1BD11BDAu;
    uint32_t x0 = k0, x1 = j + k1;
#define TFR(r) { x0 += x1; x1 = rotl32(x1,(r)); x1 ^= x0; }
    TFR(13) TFR(15) TFR(26) TFR(6)
    x0 += k1;  x1 += ks2 + 1u;
    TFR(17) TFR(29) TFR(16) TFR(24)
    x0 += ks2; x1 += k0 + 2u;
    TFR(13) TFR(15) TFR(26) TFR(6)
    x0 += k0;  x1 += k1 + 3u;
    TFR(17) TFR(29) TFR(16) TFR(24)
    x0 += k1;  x1 += ks2 + 4u;
    TFR(13) TFR(15) TFR(26) TFR(6)
    x0 += ks2; x1 += k0 + 5u;
#undef TFR
    return x0 ^ x1;
}

__device__ __forceinline__ u64 pack_vi(float v, int idx) {
    uint32_t u = __float_as_uint(v);
    u = (u & 0x80000000u) ? ~u : (u | 0x80000000u);
    return ((u64)u << 32) | (uint32_t)(0xFFFFFFFFu - (uint32_t)idx);
}

// ------------------------------ mma helpers ---------------------------------
__device__ __forceinline__ uint32_t smem_u32(const void* p) {
    uint32_t r;
    asm("{ .reg .u64 t; cvta.to.shared.u64 t, %1; cvt.u32.u64 %0, t; }" : "=r"(r) : "l"(p));
    return r;
}

__device__ __forceinline__ void mma_f16(float* c, const uint32_t* a, const uint32_t* b) {
    asm volatile("mma.sync.aligned.m16n8k16.row.col.f32.f16.f16.f32 "
        "{%0,%1,%2,%3}, {%4,%5,%6,%7}, {%8,%9}, {%0,%1,%2,%3};"
        : "+f"(c[0]), "+f"(c[1]), "+f"(c[2]), "+f"(c[3])
        : "r"(a[0]), "r"(a[1]), "r"(a[2]), "r"(a[3]), "r"(b[0]), "r"(b[1]));
}

__device__ __forceinline__ void ldsm4(uint32_t* r, uint32_t addr) {
    asm volatile("ldmatrix.sync.aligned.m8n8.x4.shared.b16 {%0,%1,%2,%3}, [%4];"
        : "=r"(r[0]), "=r"(r[1]), "=r"(r[2]), "=r"(r[3]) : "r"(addr));
}

// ------------------------------ phase A (proven) -----------------------------
__global__ void k_gemm(const float* __restrict__ Aparam, const float* __restrict__ W,
                       const float* __restrict__ bias, int K, int N, int sel) {
    const float* A = sel ? g_X : Aparam;
    float* C = sel ? g_h0 : g_X;
    int n = blockIdx.x * 32 + (threadIdx.x & 31);
    int b = blockIdx.y * 8 + (threadIdx.x >> 5);
    const float* a = A + (size_t)b * K;
    float acc = 0.f;
#pragma unroll 4
    for (int k = 0; k < K; k++) acc += a[k] * W[(size_t)k * N + n];
    C[(size_t)b * N + n] = acc + bias[n];
}

__global__ void k_lnrelu(const float* __restrict__ gam, const float* __restrict__ bet,
                         int N, int sel) {
    float* X = sel ? g_h0 : g_X;
    __shared__ float row[1024];
    __shared__ float red[256];
    int b = blockIdx.x, tid = threadIdx.x;
    float s = 0.f;
    for (int i = tid; i < N; i += 256) { float v = X[(size_t)b*N + i]; row[i] = v; s += v; }
    red[tid] = s; __syncthreads();
    for (int o = 128; o > 0; o >>= 1) { if (tid < o) red[tid] += red[tid+o]; __syncthreads(); }
    float mean = red[0] / N;
    __syncthreads();
    float ss = 0.f;
    for (int i = tid; i < N; i += 256) { float d = row[i] - mean; ss += d*d; }
    red[tid] = ss; __syncthreads();
    for (int o = 128; o > 0; o >>= 1) { if (tid < o) red[tid] += red[tid+o]; __syncthreads(); }
    float sc = rsqrtf(red[0] / N + 1e-5f);
    for (int i = tid; i < N; i += 256)
        X[(size_t)b*N + i] = fmaxf((row[i] - mean) * sc * gam[i] + bet[i], 0.f);
}

__global__ void k_init(const float* __restrict__ tok_table, float* __restrict__ out) {
    int b = blockIdx.x, tid = threadIdx.x;
    for (int i = tid; i < Hdim; i += 128) {
        float hv = g_h0[b*Hdim + i];
        g_h1[b*Hdim + i] = hv;
        split_sc(hv, &g_h1h[b*Hdim+i], &g_h1l[b*Hdim+i]);
        g_c0[b*Hdim + i] = 0.f;
        g_c1[b*Hdim + i] = 0.f;
        g_emb[b*Hdim + i] = tok_table[i];
    }
    if (tid == 0) { out[b*TOKCOLS] = 0.f; g_samp[b] = 0ull; }
}

__global__ void k_prepW(const float* __restrict__ Wo) {
    __shared__ float tile[64][65];
    int v0 = blockIdx.x * 64, k0 = blockIdx.y * 64;
    int tid = threadIdx.x, c = tid & 63, r4 = tid >> 6;
    for (int r = r4; r < 64; r += 4)
        tile[r][c] = Wo[(size_t)(k0 + r) * Vocab + v0 + c];
    __syncthreads();
    for (int r = r4; r < 64; r += 4) {
        size_t o = (size_t)(v0 + r) * Hdim + k0 + c;
        split_sc(tile[c][r], &g_WTh[o], &g_WTl[o]);
    }
}

// ------------------------- LSTM gates (R8-proven SIMT) ----------------------
__global__ void k_gates(const float* __restrict__ Wih, const float* __restrict__ Whh,
                        int layer) {
    __shared__ float As[16][128];
    __shared__ float Ws[16][32];
    int src = blockIdx.y >> 1;
    int kh  = blockIdx.y & 1;
    const float* A = (src == 0) ? (layer ? g_h0 : g_emb) : (layer ? g_h1 : g_h0);
    const float* W = (src == 0) ? Wih : Whh;
    float* part = g_part[blockIdx.y];
    int jtile = blockIdx.x * 32;
    int tid = threadIdx.x;
    int tx = tid & 15, ty = tid >> 4;
    int m0 = ty * 8, n0 = tx * 2;
    float acc[8][2] = {};
    int kbeg = kh * 256, kend = kbeg + 256;
    for (int kk = kbeg; kk < kend; kk += 16) {
#pragma unroll
        for (int i = 0; i < 2; i++) {
            int idx = tid + i * 256;
            int bb = idx >> 2, kq = idx & 3;
            float4 v = *(const float4*)&A[(size_t)bb*Hdim + kk + kq*4];
            As[kq*4+0][bb] = v.x; As[kq*4+1][bb] = v.y;
            As[kq*4+2][bb] = v.z; As[kq*4+3][bb] = v.w;
        }
        if (tid < 128) {
            int j = tid >> 2, kq = tid & 3;
            float4 v = *(const float4*)&W[(size_t)(jtile+j)*Hdim + kk + kq*4];
            Ws[kq*4+0][j] = v.x; Ws[kq*4+1][j] = v.y;
            Ws[kq*4+2][j] = v.z; Ws[kq*4+3][j] = v.w;
        }
        __syncthreads();
#pragma unroll
        for (int k = 0; k < 16; k++) {
            float4 a0 = *(const float4*)&As[k][m0];
            float4 a1 = *(const float4*)&As[k][m0+4];
            float2 wv = *(const float2*)&Ws[k][n0];
            float am[8] = {a0.x,a0.y,a0.z,a0.w,a1.x,a1.y,a1.z,a1.w};
#pragma unroll
            for (int m = 0; m < 8; m++) {
                acc[m][0] += am[m] * wv.x;
                acc[m][1] += am[m] * wv.y;
            }
        }
        __syncthreads();
    }
#pragma unroll
    for (int m = 0; m < 8; m++) {
        part[(size_t)(m0+m)*NG + jtile + n0]     = acc[m][0];
        part[(size_t)(m0+m)*NG + jtile + n0 + 1] = acc[m][1];
    }
}

__global__ void k_cell(const float* __restrict__ bih, const float* __restrict__ bhh,
                       int layer) {
    int idx = blockIdx.x * 256 + threadIdx.x;
    float* h = layer ? g_h1 : g_h0;
    float* c = layer ? g_c1 : g_c0;
    int b = idx >> 9, hh = idx & 511;
    float gs[4];
#pragma unroll
    for (int q = 0; q < 4; q++) {
        int col = hh + q * Hdim;
        float s = bih[col] + bhh[col];
#pragma unroll
        for (int p = 0; p < 4; p++) s += g_part[p][(size_t)b*NG + col];
        gs[q] = s;
    }
    float ig = 1.f / (1.f + expf(-gs[0]));
    float fg = 1.f / (1.f + expf(-gs[1]));
    float gg = tanhf(gs[2]);
    float og = 1.f / (1.f + expf(-gs[3]));
    float cn = fg * c[idx] + ig * gg;
    c[idx] = cn;
    float hn = og * tanhf(cn);
    h[idx] = hn;
    if (layer) split_sc(hn, &g_h1h[idx], &g_h1l[idx]);
}

// ---- logits mma (256 thr, 8 warps x 8 cols) + select-then-verify sampling ----
__global__ void __launch_bounds__(256, 2) k_logits_mma(
    const float* __restrict__ bo, const void* __restrict__ temp_ptr,
    float* __restrict__ out, int t, uint32_t rk0, uint32_t rk1) {
    __shared__ __align__(16) char sAh[16384], sAl[16384];
    int tid = threadIdx.x, w = tid >> 5, lane = tid & 31;
    int nbw = blockIdx.x * 64 + w * 8;     // 8 cols per warp
    uint32_t sh = smem_u32(sAh), sl = smem_u32(sAl);
    float a1[8][4] = {}, a2[8][4] = {};
    for (int ch = 0; ch < 8; ch++) {
        int cb = ch * 128;
#pragma unroll
        for (int i = 0; i < 4; i++) {
            int e = tid + i * 256;
            int row = e >> 3, seg = (e & 7) * 16;
            int so = SWZ128(row * 128 + seg);
            int go = row * 1024 + cb + seg;
            *(uint4*)(sAh + so) = *(const uint4*)((const char*)g_h1h + go);
            *(uint4*)(sAl + so) = *(const uint4*)((const char*)g_h1l + go);
        }
        __syncthreads();
#pragma unroll
        for (int ks = 0; ks < 4; ks++) {
            int kk = ch * 64 + ks * 16 + (lane & 3) * 2;
            size_t ro = (size_t)(nbw + (lane >> 2)) * Hdim + kk;
            uint32_t bh[2], bl[2];
            bh[0] = *(const uint32_t*)(g_WTh + ro);
            bh[1] = *(const uint32_t*)(g_WTh + ro + 8);
            bl[0] = *(const uint32_t*)(g_WTl + ro);
            bl[1] = *(const uint32_t*)(g_WTl + ro + 8);
#pragma unroll
            for (int m8 = 0; m8 < 8; m8++) {
                int off = SWZ128((m8 * 16 + (lane & 15)) * 128 + ks * 32 + (lane >> 4) * 16);
                uint32_t a[4];
                ldsm4(a, sh + off);
                mma_f16(a1[m8], a, bh);
                mma_f16(a2[m8], a, bl);
                ldsm4(a, sl + off);
                mma_f16(a2[m8], a, bh);
            }
        }
        __syncthreads();
    }
    uint32_t tb = *(const uint32_t*)temp_ptr;
    float temp = (tb < 0x01000000u) ? (float)(int)tb : __uint_as_float(tb);
    float inv = 1.0f / temp;
#pragma unroll
    for (int m8 = 0; m8 < 8; m8++)
#pragma unroll
        for (int r = 0; r < 2; r++) {
            int b = m8 * 16 + (lane >> 2) + r * 8;
            float* orow = out + LOGB + (size_t)(b * Steps + t) * Vocab;
            int col = nbw + (lane & 3) * 2;
            float v0 = (a1[m8][r*2]   + a2[m8][r*2]  * INVLOSCALE + bo[col])   * inv;
            float v1 = (a1[m8][r*2+1] + a2[m8][r*2+1]* INVLOSCALE + bo[col+1]) * inv;
            *(float2*)&orow[col] = make_float2(v0, v1);
            uint32_t jb = (uint32_t)(b * Vocab + col);
            float bestAk = -3.4e38f, bestF = 0.5f, bestV = 0.f;
            int bestIdx = 0;
#pragma unroll
            for (int q = 0; q < 2; q++) {
                float v = q ? v1 : v0;
                uint32_t bits = threefry_xored(rk0, rk1, jb + (uint32_t)q);
                float f = __uint_as_float((bits >> 9) | 0x3F800000u) - 1.0f;
                f = fmaxf(f + 1.1754944e-38f, 1.1754944e-38f);
                float ak = v - __logf(fmaxf(-__logf(f), 1e-37f));
                if (ak > bestAk) { bestAk = ak; bestF = f; bestV = v; bestIdx = col + q; }
            }
            float g = -logf(-logf(bestF));        // exact key for winner only
            u64 best = pack_vi(bestV + g, bestIdx);
#pragma unroll
            for (int m = 1; m < 4; m <<= 1) {
                u64 o = __shfl_xor_sync(0xFFFFFFFFu, best, m);
                if (o > best) best = o;
            }
            if ((lane & 3) == 0) atomicMax(&g_samp[b], best);
        }
}

__global__ void k_final(const float* __restrict__ tok_table, float* __restrict__ out, int t) {
    int b = blockIdx.x, tid = threadIdx.x;
    u64 p = g_samp[b];
    int idx = (int)(0xFFFFFFFFu - (uint32_t)(p & 0xFFFFFFFFull));
    __syncthreads();
    const float* rowp = tok_table + (size_t)idx * Hdim;
    for (int i = tid; i < Hdim; i += 128) g_emb[b*Hdim + i] = rowp[i];
    if (tid == 0) { out[b*TOKCOLS + (t+1)] = (float)idx; g_samp[b] = 0ull; }
}

// ------------------------------ host side ------------------------------------
static void host_threefry(uint32_t k0, uint32_t k1, uint32_t x0, uint32_t x1,
                          uint32_t& o0, uint32_t& o1) {
    uint32_t ks2 = k0 ^ k1 ^ 0x1BD11BDAu;
    x0 += k0; x1 += k1;
#define HR(r) { x0 += x1; x1 = (x1 << (r)) | (x1 >> (32 - (r))); x1 ^= x0; }
    HR(13) HR(15) HR(26) HR(6)
    x0 += k1;  x1 += ks2 + 1u;
    HR(17) HR(29) HR(16) HR(24)
    x0 += ks2; x1 += k0 + 2u;
    HR(13) HR(15) HR(26) HR(6)
    x0 += k0;  x1 += k1 + 3u;
    HR(17) HR(29) HR(16) HR(24)
    x0 += k1;  x1 += ks2 + 4u;
    HR(13) HR(15) HR(26) HR(6)
    x0 += ks2; x1 += k0 + 5u;
#undef HR
    o0 = x0; o1 = x1;
}

extern "C" void kernel_launch(void* const* d_in, const int* in_sizes, int n_in,
                              void* d_out, int out_size) {
    (void)in_sizes; (void)n_in; (void)out_size;
    const float* SE   = (const float*)d_in[0];
    const float* Wa   = (const float*)d_in[1];
    const float* ba   = (const float*)d_in[2];
    const float* g1   = (const float*)d_in[3];
    const float* b1   = (const float*)d_in[4];
    const float* Wp   = (const float*)d_in[5];
    const float* bp   = (const float*)d_in[6];
    const float* g2   = (const float*)d_in[7];
    const float* b2   = (const float*)d_in[8];
    const float* tok  = (const float*)d_in[9];
    const float* Wih0 = (const float*)d_in[10];
    const float* Whh0 = (const float*)d_in[11];
    const float* bih0 = (const float*)d_in[12];
    const float* bhh0 = (const float*)d_in[13];
    const float* Wih1 = (const float*)d_in[14];
    const float* Whh1 = (const float*)d_in[15];
    const float* bih1 = (const float*)d_in[16];
    const float* bhh1 = (const float*)d_in[17];
    const float* Wout = (const float*)d_in[18];
    const float* bout = (const float*)d_in[19];
    const void*  temp = d_in[20];
    float* out = (float*)d_out;

    // Phase A
    k_gemm<<<dim3(Edim/32, Bsz/8), 256>>>(SE, Wa, ba, Edim, Edim, 0);
    k_lnrelu<<<Bsz, 256>>>(g1, b1, Edim, 0);
    k_gemm<<<dim3(Hdim/32, Bsz/8), 256>>>(nullptr, Wp, bp, Edim, Hdim, 1);
    k_lnrelu<<<Bsz, 256>>>(g2, b2, Hdim, 1);
    k_init<<<Bsz, 128>>>(tok, out);
    k_prepW<<<dim3(Vocab/64, Hdim/64), 256>>>(Wout);

    // Phase B: 30 autoregressive steps
    for (int t = 0; t < Steps; t++) {
        uint32_t k0, k1;
        host_threefry(0u, 42u, 0u, (uint32_t)t, k0, k1);
        k_gates<<<dim3(64, 4), 256>>>(Wih0, Whh0, 0);
        k_cell<<<(Bsz*Hdim)/256, 256>>>(bih0, bhh0, 0);
        k_gates<<<dim3(64, 4), 256>>>(Wih1, Whh1, 1);
        k_cell<<<(Bsz*Hdim)/256, 256>>>(bih1, bhh1, 1);
        k_logits_mma<<<Vocab/64, 256>>>(bout, temp, out, t, k0, k1);
        k_final<<<Bsz, 128>>>(tok, out, t);
    }
}

// round 15
// speedup vs baseline: 1.1069x; 1.1069x over previous
#include <cuda_runtime.h>
#include <cuda_fp16.h>
#include <cstdint>

#define Bsz 128
#define Edim 1024
#define Hdim 512
#define Vocab 32000
#define Steps 30
#define NG 2048
#define TOKCOLS 31
#define LOGB (Bsz*TOKCOLS)
#define SWZ128(o) ((o) ^ (((o) >> 3) & 0x70))
#define LOSCALE 2048.0f
#define INVLOSCALE (1.0f/2048.0f)

typedef unsigned long long u64;

__device__ __align__(16) float g_X[Bsz*Edim];
__device__ __align__(16) float g_emb[Bsz*Hdim];
__device__ __align__(16) float g_h0[Bsz*Hdim];
__device__ __align__(16) float g_c0[Bsz*Hdim];
__device__ __align__(16) float g_h1[Bsz*Hdim];
__device__ __align__(16) float g_c1[Bsz*Hdim];
__device__ __align__(16) float g_part[4][Bsz*NG];
__device__ u64 g_samp[Bsz];
// fragment-major logits weights: [(Vocab/16) wt][8 ch][4 ks][32 lane][4 j] u32
__device__ __align__(16) uint32_t g_Bfh[(size_t)(Vocab/16)*8*4*32*4];
__device__ __align__(16) uint32_t g_Bfl[(size_t)(Vocab/16)*8*4*32*4];  // lo*2048
__device__ __align__(16) __half g_h1h[Bsz*Hdim], g_h1l[Bsz*Hdim];      // lo*2048

__device__ __forceinline__ void split_sc(float x, __half* h, __half* l) {
    __half hh = __float2half_rn(x);
    *h = hh;
    *l = __float2half_rn((x - __half2float(hh)) * LOSCALE);
}

// ------------------------- threefry (partitionable) --------------------------
__device__ __forceinline__ uint32_t rotl32(uint32_t x, int r) {
    return __funnelshift_l(x, x, r);
}

__device__ __forceinline__ uint32_t threefry_xored(uint32_t k0, uint32_t k1, uint32_t j) {
    uint32_t ks2 = k0 ^ k1 ^ 0x1BD11BDAu;
    uint32_t x0 = k0, x1 = j + k1;
#define TFR(r) { x0 += x1; x1 = rotl32(x1,(r)); x1 ^= x0; }
    TFR(13) TFR(15) TFR(26) TFR(6)
    x0 += k1;  x1 += ks2 + 1u;
    TFR(17) TFR(29) TFR(16) TFR(24)
    x0 += ks2; x1 += k0 + 2u;
    TFR(13) TFR(15) TFR(26) TFR(6)
    x0 += k0;  x1 += k1 + 3u;
    TFR(17) TFR(29) TFR(16) TFR(24)
    x0 += k1;  x1 += ks2 + 4u;
    TFR(13) TFR(15) TFR(26) TFR(6)
    x0 += ks2; x1 += k0 + 5u;
#undef TFR
    return x0 ^ x1;
}

__device__ __forceinline__ u64 pack_vi(float v, int idx) {
    uint32_t u = __float_as_uint(v);
    u = (u & 0x80000000u) ? ~u : (u | 0x80000000u);
    return ((u64)u << 32) | (uint32_t)(0xFFFFFFFFu - (uint32_t)idx);
}

// ------------------------------ mma helpers ---------------------------------
__device__ __forceinline__ uint32_t smem_u32(const void* p) {
    uint32_t r;
    asm("{ .reg .u64 t; cvta.to.shared.u64 t, %1; cvt.u32.u64 %0, t; }" : "=r"(r) : "l"(p));
    return r;
}

__device__ __forceinline__ void mma_f16(float* c, const uint32_t* a, const uint32_t* b) {
    asm volatile("mma.sync.aligned.m16n8k16.row.col.f32.f16.f16.f32 "
        "{%0,%1,%2,%3}, {%4,%5,%6,%7}, {%8,%9}, {%0,%1,%2,%3};"
        : "+f"(c[0]), "+f"(c[1]), "+f"(c[2]), "+f"(c[3])
        : "r"(a[0]), "r"(a[1]), "r"(a[2]), "r"(a[3]), "r"(b[0]), "r"(b[1]));
}

__device__ __forceinline__ void ldsm4(uint32_t* r, uint32_t addr) {
    asm volatile("ldmatrix.sync.aligned.m8n8.x4.shared.b16 {%0,%1,%2,%3}, [%4];"
        : "=r"(r[0]), "=r"(r[1]), "=r"(r[2]), "=r"(r[3]) : "r"(addr));
}

// ------------------------------ phase A (proven) -----------------------------
__global__ void k_gemm(const float* __restrict__ Aparam, const float* __restrict__ W,
                       const float* __restrict__ bias, int K, int N, int sel) {
    const float* A = sel ? g_X : Aparam;
    float* C = sel ? g_h0 : g_X;
    int n = blockIdx.x * 32 + (threadIdx.x & 31);
    int b = blockIdx.y * 8 + (threadIdx.x >> 5);
    const float* a = A + (size_t)b * K;
    float acc = 0.f;
#pragma unroll 4
    for (int k = 0; k < K; k++) acc += a[k] * W[(size_t)k * N + n];
    C[(size_t)b * N + n] = acc + bias[n];
}

__global__ void k_lnrelu(const float* __restrict__ gam, const float* __restrict__ bet,
                         int N, int sel) {
    float* X = sel ? g_h0 : g_X;
    __shared__ float row[1024];
    __shared__ float red[256];
    int b = blockIdx.x, tid = threadIdx.x;
    float s = 0.f;
    for (int i = tid; i < N; i += 256) { float v = X[(size_t)b*N + i]; row[i] = v; s += v; }
    red[tid] = s; __syncthreads();
    for (int o = 128; o > 0; o >>= 1) { if (tid < o) red[tid] += red[tid+o]; __syncthreads(); }
    float mean = red[0] / N;
    __syncthreads();
    float ss = 0.f;
    for (int i = tid; i < N; i += 256) { float d = row[i] - mean; ss += d*d; }
    red[tid] = ss; __syncthreads();
    for (int o = 128; o > 0; o >>= 1) { if (tid < o) red[tid] += red[tid+o]; __syncthreads(); }
    float sc = rsqrtf(red[0] / N + 1e-5f);
    for (int i = tid; i < N; i += 256)
        X[(size_t)b*N + i] = fmaxf((row[i] - mean) * sc * gam[i] + bet[i], 0.f);
}

__global__ void k_init(const float* __restrict__ tok_table, float* __restrict__ out) {
    int b = blockIdx.x, tid = threadIdx.x;
    for (int i = tid; i < Hdim; i += 128) {
        float hv = g_h0[b*Hdim + i];
        g_h1[b*Hdim + i] = hv;
        split_sc(hv, &g_h1h[b*Hdim+i], &g_h1l[b*Hdim+i]);
        g_c0[b*Hdim + i] = 0.f;
        g_c1[b*Hdim + i] = 0.f;
        g_emb[b*Hdim + i] = tok_table[i];
    }
    if (tid == 0) { out[b*TOKCOLS] = 0.f; g_samp[b] = 0ull; }
}

// Wout [512, 32000] -> fragment-major split fp16 layout (hi, lo*2048)
__global__ void k_prepW(const float* __restrict__ Wo) {
    __shared__ float tile[64][65];
    int v0 = blockIdx.x * 64, k0 = blockIdx.y * 64;
    int tid = threadIdx.x, c = tid & 63, r4 = tid >> 6;
    for (int r = r4; r < 64; r += 4)
        tile[r][c] = Wo[(size_t)(k0 + r) * Vocab + v0 + c];
    __syncthreads();
    // write 2048 u32 fragments (hi + lo) for this 64v x 64k tile
    for (int idx = tid; idx < 2048; idx += 256) {
        int j = idx & 3, lane = (idx >> 2) & 31, ks = (idx >> 7) & 3, wl = idx >> 9;
        int nt = j >> 1, piece = j & 1;
        int vloc = wl * 16 + nt * 8 + (lane >> 2);
        int kloc = ks * 16 + (lane & 3) * 2 + piece * 8;
        float f0 = tile[kloc][vloc], f1 = tile[kloc + 1][vloc];
        __half h0, l0, h1, l1;
        split_sc(f0, &h0, &l0);
        split_sc(f1, &h1, &l1);
        uint32_t uh = (uint32_t)__half_as_ushort(h0) | ((uint32_t)__half_as_ushort(h1) << 16);
        uint32_t ul = (uint32_t)__half_as_ushort(l0) | ((uint32_t)__half_as_ushort(l1) << 16);
        size_t gidx = ((((size_t)(blockIdx.x * 4 + wl) * 8 + blockIdx.y) * 4 + ks) * 32 + lane) * 4 + j;
        g_Bfh[gidx] = uh;
        g_Bfl[gidx] = ul;
    }
}

// ------------------------- LSTM gates (R8-proven SIMT) ----------------------
__global__ void k_gates(const float* __restrict__ Wih, const float* __restrict__ Whh,
                        int layer) {
    __shared__ float As[16][128];
    __shared__ float Ws[16][32];
    int src = blockIdx.y >> 1;
    int kh  = blockIdx.y & 1;
    const float* A = (src == 0) ? (layer ? g_h0 : g_emb) : (layer ? g_h1 : g_h0);
    const float* W = (src == 0) ? Wih : Whh;
    float* part = g_part[blockIdx.y];
    int jtile = blockIdx.x * 32;
    int tid = threadIdx.x;
    int tx = tid & 15, ty = tid >> 4;
    int m0 = ty * 8, n0 = tx * 2;
    float acc[8][2] = {};
    int kbeg = kh * 256, kend = kbeg + 256;
    for (int kk = kbeg; kk < kend; kk += 16) {
#pragma unroll
        for (int i = 0; i < 2; i++) {
            int idx = tid + i * 256;
            int bb = idx >> 2, kq = idx & 3;
            float4 v = *(const float4*)&A[(size_t)bb*Hdim + kk + kq*4];
            As[kq*4+0][bb] = v.x; As[kq*4+1][bb] = v.y;
            As[kq*4+2][bb] = v.z; As[kq*4+3][bb] = v.w;
        }
        if (tid < 128) {
            int j = tid >> 2, kq = tid & 3;
            float4 v = *(const float4*)&W[(size_t)(jtile+j)*Hdim + kk + kq*4];
            Ws[kq*4+0][j] = v.x; Ws[kq*4+1][j] = v.y;
            Ws[kq*4+2][j] = v.z; Ws[kq*4+3][j] = v.w;
        }
        __syncthreads();
#pragma unroll
        for (int k = 0; k < 16; k++) {
            float4 a0 = *(const float4*)&As[k][m0];
            float4 a1 = *(const float4*)&As[k][m0+4];
            float2 wv = *(const float2*)&Ws[k][n0];
            float am[8] = {a0.x,a0.y,a0.z,a0.w,a1.x,a1.y,a1.z,a1.w};
#pragma unroll
            for (int m = 0; m < 8; m++) {
                acc[m][0] += am[m] * wv.x;
                acc[m][1] += am[m] * wv.y;
            }
        }
        __syncthreads();
    }
#pragma unroll
    for (int m = 0; m < 8; m++) {
        part[(size_t)(m0+m)*NG + jtile + n0]     = acc[m][0];
        part[(size_t)(m0+m)*NG + jtile + n0 + 1] = acc[m][1];
    }
}

__global__ void k_cell(const float* __restrict__ bih, const float* __restrict__ bhh,
                       int layer) {
    int idx = blockIdx.x * 256 + threadIdx.x;
    float* h = layer ? g_h1 : g_h0;
    float* c = layer ? g_c1 : g_c0;
    int b = idx >> 9, hh = idx & 511;
    float gs[4];
#pragma unroll
    for (int q = 0; q < 4; q++) {
        int col = hh + q * Hdim;
        float s = bih[col] + bhh[col];
#pragma unroll
        for (int p = 0; p < 4; p++) s += g_part[p][(size_t)b*NG + col];
        gs[q] = s;
    }
    float ig = 1.f / (1.f + expf(-gs[0]));
    float fg = 1.f / (1.f + expf(-gs[1]));
    float gg = tanhf(gs[2]);
    float og = 1.f / (1.f + expf(-gs[3]));
    float cn = fg * c[idx] + ig * gg;
    c[idx] = cn;
    float hn = og * tanhf(cn);
    h[idx] = hn;
    if (layer) split_sc(hn, &g_h1h[idx], &g_h1l[idx]);
}

// -------------- logits mma + select-then-verify sampling ---------------------
__global__ void __launch_bounds__(128) k_logits_mma(
    const float* __restrict__ bo, const void* __restrict__ temp_ptr,
    float* __restrict__ out, int t, uint32_t rk0, uint32_t rk1) {
    __shared__ __align__(16) char sAh[16384], sAl[16384];
    int tid = threadIdx.x, w = tid >> 5, lane = tid & 31;
    int nb = blockIdx.x * 64 + w * 16;
    uint32_t sh = smem_u32(sAh), sl = smem_u32(sAl);
    float a1[8][2][4] = {}, a2[8][2][4] = {};
    for (int ch = 0; ch < 8; ch++) {
        int cb = ch * 128;
#pragma unroll
        for (int i = 0; i < 8; i++) {
            int e = tid + i * 128;
            int row = e >> 3, seg = (e & 7) * 16;
            int so = SWZ128(row * 128 + seg);
            int go = row * 1024 + cb + seg;
            *(uint4*)(sAh + so) = *(const uint4*)((const char*)g_h1h + go);
            *(uint4*)(sAl + so) = *(const uint4*)((const char*)g_h1l + go);
        }
        __syncthreads();
#pragma unroll
        for (int ks = 0; ks < 4; ks++) {
            size_t fidx = ((((size_t)(blockIdx.x * 4 + w) * 8 + ch) * 4 + ks) * 32 + lane) * 4;
            uint4 BH = *(const uint4*)(g_Bfh + fidx);
            uint4 BL = *(const uint4*)(g_Bfl + fidx);
            uint32_t bh[2][2] = {{BH.x, BH.y}, {BH.z, BH.w}};
            uint32_t bl[2][2] = {{BL.x, BL.y}, {BL.z, BL.w}};
#pragma unroll
            for (int m8 = 0; m8 < 8; m8++) {
                int off = SWZ128((m8 * 16 + (lane & 15)) * 128 + ks * 32 + (lane >> 4) * 16);
                uint32_t a[4];
                ldsm4(a, sh + off);
#pragma unroll
                for (int nt = 0; nt < 2; nt++) {
                    mma_f16(a1[m8][nt], a, bh[nt]);
                    mma_f16(a2[m8][nt], a, bl[nt]);
                }
                ldsm4(a, sl + off);
#pragma unroll
                for (int nt = 0; nt < 2; nt++)
                    mma_f16(a2[m8][nt], a, bh[nt]);
            }
        }
        __syncthreads();
    }
    uint32_t tb = *(const uint32_t*)temp_ptr;
    float temp = (tb < 0x01000000u) ? (float)(int)tb : __uint_as_float(tb);
    float inv = 1.0f / temp;
#pragma unroll
    for (int m8 = 0; m8 < 8; m8++)
#pragma unroll
        for (int r = 0; r < 2; r++) {
            int b = m8 * 16 + (lane >> 2) + r * 8;
            float* orow = out + LOGB + (size_t)(b * Steps + t) * Vocab;
            float bestAk = -3.4e38f, bestF = 0.5f, bestV = 0.f;
            int bestIdx = 0;
#pragma unroll
            for (int nt = 0; nt < 2; nt++) {
                int col = nb + nt * 8 + (lane & 3) * 2;
                float v0 = (a1[m8][nt][r*2]   + a2[m8][nt][r*2]  * INVLOSCALE + bo[col])   * inv;
                float v1 = (a1[m8][nt][r*2+1] + a2[m8][nt][r*2+1]* INVLOSCALE + bo[col+1]) * inv;
                *(float2*)&orow[col] = make_float2(v0, v1);
                uint32_t jb = (uint32_t)(b * Vocab + col);
#pragma unroll
                for (int q = 0; q < 2; q++) {
                    float v = q ? v1 : v0;
                    uint32_t bits = threefry_xored(rk0, rk1, jb + (uint32_t)q);
                    float f = __uint_as_float((bits >> 9) | 0x3F800000u) - 1.0f;
                    f = fmaxf(f + 1.1754944e-38f, 1.1754944e-38f);
                    // cheap approximate key (MUFU) — selection only
                    float ak = v - __logf(fmaxf(-__logf(f), 1e-37f));
                    if (ak > bestAk) { bestAk = ak; bestF = f; bestV = v; bestIdx = col + q; }
                }
            }
            // exact key (bit-identical to reference formula) for the winner only
            float g = -logf(-logf(bestF));
            u64 best = pack_vi(bestV + g, bestIdx);
#pragma unroll
            for (int m = 1; m < 4; m <<= 1) {
                u64 o = __shfl_xor_sync(0xFFFFFFFFu, best, m);
                if (o > best) best = o;
            }
            if ((lane & 3) == 0) atomicMax(&g_samp[b], best);
        }
}

__global__ void k_final(const float* __restrict__ tok_table, float* __restrict__ out, int t) {
    int b = blockIdx.x, tid = threadIdx.x;
    u64 p = g_samp[b];
    int idx = (int)(0xFFFFFFFFu - (uint32_t)(p & 0xFFFFFFFFull));
    __syncthreads();
    const float* rowp = tok_table + (size_t)idx * Hdim;
    for (int i = tid; i < Hdim; i += 128) g_emb[b*Hdim + i] = rowp[i];
    if (tid == 0) { out[b*TOKCOLS + (t+1)] = (float)idx; g_samp[b] = 0ull; }
}

// ------------------------------ host side ------------------------------------
static void host_threefry(uint32_t k0, uint32_t k1, uint32_t x0, uint32_t x1,
                          uint32_t& o0, uint32_t& o1) {
    uint32_t ks2 = k0 ^ k1 ^ 0x1BD11BDAu;
    x0 += k0; x1 += k1;
#define HR(r) { x0 += x1; x1 = (x1 << (r)) | (x1 >> (32 - (r))); x1 ^= x0; }
    HR(13) HR(15) HR(26) HR(6)
    x0 += k1;  x1 += ks2 + 1u;
    HR(17) HR(29) HR(16) HR(24)
    x0 += ks2; x1 += k0 + 2u;
    HR(13) HR(15) HR(26) HR(6)
    x0 += k0;  x1 += k1 + 3u;
    HR(17) HR(29) HR(16) HR(24)
    x0 += k1;  x1 += ks2 + 4u;
    HR(13) HR(15) HR(26) HR(6)
    x0 += ks2; x1 += k0 + 5u;
#undef HR
    o0 = x0; o1 = x1;
}

extern "C" void kernel_launch(void* const* d_in, const int* in_sizes, int n_in,
                              void* d_out, int out_size) {
    (void)in_sizes; (void)n_in; (void)out_size;
    const float* SE   = (const float*)d_in[0];
    const float* Wa   = (const float*)d_in[1];
    const float* ba   = (const float*)d_in[2];
    const float* g1   = (const float*)d_in[3];
    const float* b1   = (const float*)d_in[4];
    const float* Wp   = (const float*)d_in[5];
    const float* bp   = (const float*)d_in[6];
    const float* g2   = (const float*)d_in[7];
    const float* b2   = (const float*)d_in[8];
    const float* tok  = (const float*)d_in[9];
    const float* Wih0 = (const float*)d_in[10];
    const float* Whh0 = (const float*)d_in[11];
    const float* bih0 = (const float*)d_in[12];
    const float* bhh0 = (const float*)d_in[13];
    const float* Wih1 = (const float*)d_in[14];
    const float* Whh1 = (const float*)d_in[15];
    const float* bih1 = (const float*)d_in[16];
    const float* bhh1 = (const float*)d_in[17];
    const float* Wout = (const float*)d_in[18];
    const float* bout = (const float*)d_in[19];
    const void*  temp = d_in[20];
    float* out = (float*)d_out;

    // Phase A
    k_gemm<<<dim3(Edim/32, Bsz/8), 256>>>(SE, Wa, ba, Edim, Edim, 0);
    k_lnrelu<<<Bsz, 256>>>(g1, b1, Edim, 0);
    k_gemm<<<dim3(Hdim/32, Bsz/8), 256>>>(nullptr, Wp, bp, Edim, Hdim, 1);
    k_lnrelu<<<Bsz, 256>>>(g2, b2, Hdim, 1);
    k_init<<<Bsz, 128>>>(tok, out);
    k_prepW<<<dim3(Vocab/64, Hdim/64), 256>>>(Wout);

    // Phase B: 30 autoregressive steps
    for (int t = 0; t < Steps; t++) {
        uint32_t k0, k1;
        host_threefry(0u, 42u, 0u, (uint32_t)t, k0, k1);
        k_gates<<<dim3(64, 4), 256>>>(Wih0, Whh0, 0);
        k_cell<<<(Bsz*Hdim)/256, 256>>>(bih0, bhh0, 0);
        k_gates<<<dim3(64, 4), 256>>>(Wih1, Whh1, 1);
        k_cell<<<(Bsz*Hdim)/256, 256>>>(bih1, bhh1, 1);
        k_logits_mma<<<Vocab/64, 128>>>(bout, temp, out, t, k0, k1);
        k_final<<<Bsz, 128>>>(tok, out, t);
    }
}

// round 16
// speedup vs baseline: 1.1917x; 1.0766x over previous
#include <cuda_runtime.h>
#include <cuda_fp16.h>
#include <cstdint>

#define Bsz 128
#define Edim 1024
#define Hdim 512
#define Vocab 32000
#define Steps 30
#define NG 2048
#define TOKCOLS 31
#define LOGB (Bsz*TOKCOLS)
#define SWZ128(o) ((o) ^ (((o) >> 3) & 0x70))
#define LOSCALE 2048.0f
#define INVLOSCALE (1.0f/2048.0f)

typedef unsigned long long u64;

__device__ __align__(16) float g_X[Bsz*Edim];
__device__ __align__(16) float g_emb[Bsz*Hdim];
__device__ __align__(16) float g_h0[Bsz*Hdim];
__device__ __align__(16) float g_c0[Bsz*Hdim];
__device__ __align__(16) float g_h1[Bsz*Hdim];
__device__ __align__(16) float g_c1[Bsz*Hdim];
__device__ __align__(16) float g_part[8][Bsz*NG];
__device__ u64 g_samp[Bsz];
// fragment-major logits weights: [(Vocab/16) wt][8 ch][4 ks][32 lane][4 j] u32
__device__ __align__(16) uint32_t g_Bfh[(size_t)(Vocab/16)*8*4*32*4];
__device__ __align__(16) uint32_t g_Bfl[(size_t)(Vocab/16)*8*4*32*4];  // lo*2048
__device__ __align__(16) __half g_h1h[Bsz*Hdim], g_h1l[Bsz*Hdim];      // lo*2048

__device__ __forceinline__ void split_sc(float x, __half* h, __half* l) {
    __half hh = __float2half_rn(x);
    *h = hh;
    *l = __float2half_rn((x - __half2float(hh)) * LOSCALE);
}

// ------------------------- threefry (partitionable) --------------------------
__device__ __forceinline__ uint32_t rotl32(uint32_t x, int r) {
    return __funnelshift_l(x, x, r);
}

__device__ __forceinline__ uint32_t threefry_xored(uint32_t k0, uint32_t k1, uint32_t j) {
    uint32_t ks2 = k0 ^ k1 ^ 0x1BD11BDAu;
    uint32_t x0 = k0, x1 = j + k1;
#define TFR(r) { x0 += x1; x1 = rotl32(x1,(r)); x1 ^= x0; }
    TFR(13) TFR(15) TFR(26) TFR(6)
    x0 += k1;  x1 += ks2 + 1u;
    TFR(17) TFR(29) TFR(16) TFR(24)
    x0 += ks2; x1 += k0 + 2u;
    TFR(13) TFR(15) TFR(26) TFR(6)
    x0 += k0;  x1 += k1 + 3u;
    TFR(17) TFR(29) TFR(16) TFR(24)
    x0 += k1;  x1 += ks2 + 4u;
    TFR(13) TFR(15) TFR(26) TFR(6)
    x0 += ks2; x1 += k0 + 5u;
#undef TFR
    return x0 ^ x1;
}

__device__ __forceinline__ u64 pack_vi(float v, int idx) {
    uint32_t u = __float_as_uint(v);
    u = (u & 0x80000000u) ? ~u : (u | 0x80000000u);
    return ((u64)u << 32) | (uint32_t)(0xFFFFFFFFu - (uint32_t)idx);
}

// ------------------------------ mma helpers ---------------------------------
__device__ __forceinline__ uint32_t smem_u32(const void* p) {
    uint32_t r;
    asm("{ .reg .u64 t; cvta.to.shared.u64 t, %1; cvt.u32.u64 %0, t; }" : "=r"(r) : "l"(p));
    return r;
}

__device__ __forceinline__ void mma_f16(float* c, const uint32_t* a, const uint32_t* b) {
    asm volatile("mma.sync.aligned.m16n8k16.row.col.f32.f16.f16.f32 "
        "{%0,%1,%2,%3}, {%4,%5,%6,%7}, {%8,%9}, {%0,%1,%2,%3};"
        : "+f"(c[0]), "+f"(c[1]), "+f"(c[2]), "+f"(c[3])
        : "r"(a[0]), "r"(a[1]), "r"(a[2]), "r"(a[3]), "r"(b[0]), "r"(b[1]));
}

__device__ __forceinline__ void ldsm4(uint32_t* r, uint32_t addr) {
    asm volatile("ldmatrix.sync.aligned.m8n8.x4.shared.b16 {%0,%1,%2,%3}, [%4];"
        : "=r"(r[0]), "=r"(r[1]), "=r"(r[2]), "=r"(r[3]) : "r"(addr));
}

// ------------------------------ phase A (proven) -----------------------------
__global__ void k_gemm(const float* __restrict__ Aparam, const float* __restrict__ W,
                       const float* __restrict__ bias, int K, int N, int sel) {
    const float* A = sel ? g_X : Aparam;
    float* C = sel ? g_h0 : g_X;
    int n = blockIdx.x * 32 + (threadIdx.x & 31);
    int b = blockIdx.y * 8 + (threadIdx.x >> 5);
    const float* a = A + (size_t)b * K;
    float acc = 0.f;
#pragma unroll 4
    for (int k = 0; k < K; k++) acc += a[k] * W[(size_t)k * N + n];
    C[(size_t)b * N + n] = acc + bias[n];
}

__global__ void k_lnrelu(const float* __restrict__ gam, const float* __restrict__ bet,
                         int N, int sel) {
    float* X = sel ? g_h0 : g_X;
    __shared__ float row[1024];
    __shared__ float red[256];
    int b = blockIdx.x, tid = threadIdx.x;
    float s = 0.f;
    for (int i = tid; i < N; i += 256) { float v = X[(size_t)b*N + i]; row[i] = v; s += v; }
    red[tid] = s; __syncthreads();
    for (int o = 128; o > 0; o >>= 1) { if (tid < o) red[tid] += red[tid+o]; __syncthreads(); }
    float mean = red[0] / N;
    __syncthreads();
    float ss = 0.f;
    for (int i = tid; i < N; i += 256) { float d = row[i] - mean; ss += d*d; }
    red[tid] = ss; __syncthreads();
    for (int o = 128; o > 0; o >>= 1) { if (tid < o) red[tid] += red[tid+o]; __syncthreads(); }
    float sc = rsqrtf(red[0] / N + 1e-5f);
    for (int i = tid; i < N; i += 256)
        X[(size_t)b*N + i] = fmaxf((row[i] - mean) * sc * gam[i] + bet[i], 0.f);
}

__global__ void k_init(const float* __restrict__ tok_table, float* __restrict__ out) {
    int b = blockIdx.x, tid = threadIdx.x;
    for (int i = tid; i < Hdim; i += 128) {
        float hv = g_h0[b*Hdim + i];
        g_h1[b*Hdim + i] = hv;
        split_sc(hv, &g_h1h[b*Hdim+i], &g_h1l[b*Hdim+i]);
        g_c0[b*Hdim + i] = 0.f;
        g_c1[b*Hdim + i] = 0.f;
        g_emb[b*Hdim + i] = tok_table[i];
    }
    if (tid == 0) { out[b*TOKCOLS] = 0.f; g_samp[b] = 0ull; }
}

// Wout [512, 32000] -> fragment-major split fp16 layout (hi, lo*2048)
__global__ void k_prepW(const float* __restrict__ Wo) {
    __shared__ float tile[64][65];
    int v0 = blockIdx.x * 64, k0 = blockIdx.y * 64;
    int tid = threadIdx.x, c = tid & 63, r4 = tid >> 6;
    for (int r = r4; r < 64; r += 4)
        tile[r][c] = Wo[(size_t)(k0 + r) * Vocab + v0 + c];
    __syncthreads();
    for (int idx = tid; idx < 2048; idx += 256) {
        int j = idx & 3, lane = (idx >> 2) & 31, ks = (idx >> 7) & 3, wl = idx >> 9;
        int nt = j >> 1, piece = j & 1;
        int vloc = wl * 16 + nt * 8 + (lane >> 2);
        int kloc = ks * 16 + (lane & 3) * 2 + piece * 8;
        float f0 = tile[kloc][vloc], f1 = tile[kloc + 1][vloc];
        __half h0, l0, h1, l1;
        split_sc(f0, &h0, &l0);
        split_sc(f1, &h1, &l1);
        uint32_t uh = (uint32_t)__half_as_ushort(h0) | ((uint32_t)__half_as_ushort(h1) << 16);
        uint32_t ul = (uint32_t)__half_as_ushort(l0) | ((uint32_t)__half_as_ushort(l1) << 16);
        size_t gidx = ((((size_t)(blockIdx.x * 4 + wl) * 8 + blockIdx.y) * 4 + ks) * 32 + lane) * 4 + j;
        g_Bfh[gidx] = uh;
        g_Bfl[gidx] = ul;
    }
}

// ------------------- LSTM gates (SIMT, BN=64 BK=128, R11-proven) -------------
__global__ void k_gates(const float* __restrict__ Wih, const float* __restrict__ Whh,
                        int layer) {
    __shared__ float As[16][128];
    __shared__ float Ws[16][64];
    int p = blockIdx.y;                 // 0..7
    int src = p >> 2, kseg = p & 3;
    const float* A = (src == 0) ? (layer ? g_h0 : g_emb) : (layer ? g_h1 : g_h0);
    const float* W = (src == 0) ? Wih : Whh;
    float* part = g_part[p];
    int jtile = blockIdx.x * 64;        // grid.x = 32
    int tid = threadIdx.x;
    int tx = tid & 15, ty = tid >> 4;
    int m0 = ty * 8, n0 = tx * 4;
    float acc[8][4] = {};
    int kbeg = kseg * 128, kend = kbeg + 128;
    for (int kk = kbeg; kk < kend; kk += 16) {
#pragma unroll
        for (int i = 0; i < 2; i++) {
            int idx = tid + i * 256;
            int bb = idx >> 2, kq = idx & 3;
            float4 v = *(const float4*)&A[(size_t)bb*Hdim + kk + kq*4];
            As[kq*4+0][bb] = v.x; As[kq*4+1][bb] = v.y;
            As[kq*4+2][bb] = v.z; As[kq*4+3][bb] = v.w;
        }
        {
            int j = tid >> 2, kq = tid & 3;
            float4 v = *(const float4*)&W[(size_t)(jtile+j)*Hdim + kk + kq*4];
            Ws[kq*4+0][j] = v.x; Ws[kq*4+1][j] = v.y;
            Ws[kq*4+2][j] = v.z; Ws[kq*4+3][j] = v.w;
        }
        __syncthreads();
#pragma unroll
        for (int k = 0; k < 16; k++) {
            float4 a0 = *(const float4*)&As[k][m0];
            float4 a1 = *(const float4*)&As[k][m0+4];
            float4 wv = *(const float4*)&Ws[k][n0];
            float am[8] = {a0.x,a0.y,a0.z,a0.w,a1.x,a1.y,a1.z,a1.w};
#pragma unroll
            for (int m = 0; m < 8; m++) {
                acc[m][0] += am[m]*wv.x; acc[m][1] += am[m]*wv.y;
                acc[m][2] += am[m]*wv.z; acc[m][3] += am[m]*wv.w;
            }
        }
        __syncthreads();
    }
#pragma unroll
    for (int m = 0; m < 8; m++)
        *(float4*)&part[(size_t)(m0+m)*NG + jtile + n0] = *(float4*)acc[m];
}

__global__ void k_cell(const float* __restrict__ bih, const float* __restrict__ bhh,
                       int layer) {
    int idx = blockIdx.x * 256 + threadIdx.x;
    float* h = layer ? g_h1 : g_h0;
    float* c = layer ? g_c1 : g_c0;
    int b = idx >> 9, hh = idx & 511;
    float gs[4];
#pragma unroll
    for (int q = 0; q < 4; q++) {
        int col = hh + q * Hdim;
        float s = bih[col] + bhh[col];
#pragma unroll
        for (int p = 0; p < 8; p++) s += g_part[p][(size_t)b*NG + col];
        gs[q] = s;
    }
    float ig = 1.f / (1.f + expf(-gs[0]));
    float fg = 1.f / (1.f + expf(-gs[1]));
    float gg = tanhf(gs[2]);
    float og = 1.f / (1.f + expf(-gs[3]));
    float cn = fg * c[idx] + ig * gg;
    c[idx] = cn;
    float hn = og * tanhf(cn);
    h[idx] = hn;
    if (layer) split_sc(hn, &g_h1h[idx], &g_h1l[idx]);
}

// -------------- logits mma + select-then-verify sampling ---------------------
__global__ void __launch_bounds__(128) k_logits_mma(
    const float* __restrict__ bo, const void* __restrict__ temp_ptr,
    float* __restrict__ out, int t, uint32_t rk0, uint32_t rk1) {
    __shared__ __align__(16) char sAh[16384], sAl[16384];
    int tid = threadIdx.x, w = tid >> 5, lane = tid & 31;
    int nb = blockIdx.x * 64 + w * 16;
    uint32_t sh = smem_u32(sAh), sl = smem_u32(sAl);
    float a1[8][2][4] = {}, a2[8][2][4] = {};
    for (int ch = 0; ch < 8; ch++) {
        int cb = ch * 128;
#pragma unroll
        for (int i = 0; i < 8; i++) {
            int e = tid + i * 128;
            int row = e >> 3, seg = (e & 7) * 16;
            int so = SWZ128(row * 128 + seg);
            int go = row * 1024 + cb + seg;
            *(uint4*)(sAh + so) = *(const uint4*)((const char*)g_h1h + go);
            *(uint4*)(sAl + so) = *(const uint4*)((const char*)g_h1l + go);
        }
        __syncthreads();
#pragma unroll
        for (int ks = 0; ks < 4; ks++) {
            size_t fidx = ((((size_t)(blockIdx.x * 4 + w) * 8 + ch) * 4 + ks) * 32 + lane) * 4;
            uint4 BH = *(const uint4*)(g_Bfh + fidx);
            uint4 BL = *(const uint4*)(g_Bfl + fidx);
            uint32_t bh[2][2] = {{BH.x, BH.y}, {BH.z, BH.w}};
            uint32_t bl[2][2] = {{BL.x, BL.y}, {BL.z, BL.w}};
#pragma unroll
            for (int m8 = 0; m8 < 8; m8++) {
                int off = SWZ128((m8 * 16 + (lane & 15)) * 128 + ks * 32 + (lane >> 4) * 16);
                uint32_t a[4];
                ldsm4(a, sh + off);
#pragma unroll
                for (int nt = 0; nt < 2; nt++) {
                    mma_f16(a1[m8][nt], a, bh[nt]);
                    mma_f16(a2[m8][nt], a, bl[nt]);
                }
                ldsm4(a, sl + off);
#pragma unroll
                for (int nt = 0; nt < 2; nt++)
                    mma_f16(a2[m8][nt], a, bh[nt]);
            }
        }
        __syncthreads();
    }
    uint32_t tb = *(const uint32_t*)temp_ptr;
    float temp = (tb < 0x01000000u) ? (float)(int)tb : __uint_as_float(tb);
    float inv = 1.0f / temp;
#pragma unroll
    for (int m8 = 0; m8 < 8; m8++)
#pragma unroll
        for (int r = 0; r < 2; r++) {
            int b = m8 * 16 + (lane >> 2) + r * 8;
            float* orow = out + LOGB + (size_t)(b * Steps + t) * Vocab;
            float bestAk = -3.4e38f, bestF = 0.5f, bestV = 0.f;
            int bestIdx = 0;
#pragma unroll
            for (int nt = 0; nt < 2; nt++) {
                int col = nb + nt * 8 + (lane & 3) * 2;
                float v0 = (a1[m8][nt][r*2]   + a2[m8][nt][r*2]  * INVLOSCALE + bo[col])   * inv;
                float v1 = (a1[m8][nt][r*2+1] + a2[m8][nt][r*2+1]* INVLOSCALE + bo[col+1]) * inv;
                *(float2*)&orow[col] = make_float2(v0, v1);
                uint32_t jb = (uint32_t)(b * Vocab + col);
#pragma unroll
                for (int q = 0; q < 2; q++) {
                    float v = q ? v1 : v0;
                    uint32_t bits = threefry_xored(rk0, rk1, jb + (uint32_t)q);
                    float f = __uint_as_float((bits >> 9) | 0x3F800000u) - 1.0f;
                    f = fmaxf(f + 1.1754944e-38f, 1.1754944e-38f);
                    float ak = v - __logf(fmaxf(-__logf(f), 1e-37f));
                    if (ak > bestAk) { bestAk = ak; bestF = f; bestV = v; bestIdx = col + q; }
                }
            }
            float g = -logf(-logf(bestF));   // exact key for winner only
            u64 best = pack_vi(bestV + g, bestIdx);
#pragma unroll
            for (int m = 1; m < 4; m <<= 1) {
                u64 o = __shfl_xor_sync(0xFFFFFFFFu, best, m);
                if (o > best) best = o;
            }
            if ((lane & 3) == 0) atomicMax(&g_samp[b], best);
        }
}

__global__ void k_final(const float* __restrict__ tok_table, float* __restrict__ out, int t) {
    int b = blockIdx.x, tid = threadIdx.x;
    u64 p = g_samp[b];
    int idx = (int)(0xFFFFFFFFu - (uint32_t)(p & 0xFFFFFFFFull));
    __syncthreads();
    const float* rowp = tok_table + (size_t)idx * Hdim;
    for (int i = tid; i < Hdim; i += 128) g_emb[b*Hdim + i] = rowp[i];
    if (tid == 0) { out[b*TOKCOLS + (t+1)] = (float)idx; g_samp[b] = 0ull; }
}

// ------------------------------ host side ------------------------------------
static void host_threefry(uint32_t k0, uint32_t k1, uint32_t x0, uint32_t x1,
                          uint32_t& o0, uint32_t& o1) {
    uint32_t ks2 = k0 ^ k1 ^ 0x1BD11BDAu;
    x0 += k0; x1 += k1;
#define HR(r) { x0 += x1; x1 = (x1 << (r)) | (x1 >> (32 - (r))); x1 ^= x0; }
    HR(13) HR(15) HR(26) HR(6)
    x0 += k1;  x1 += ks2 + 1u;
    HR(17) HR(29) HR(16) HR(24)
    x0 += ks2; x1 += k0 + 2u;
    HR(13) HR(15) HR(26) HR(6)
    x0 += k0;  x1 += k1 + 3u;
    HR(17) HR(29) HR(16) HR(24)
    x0 += k1;  x1 += ks2 + 4u;
    HR(13) HR(15) HR(26) HR(6)
    x0 += ks2; x1 += k0 + 5u;
#undef HR
    o0 = x0; o1 = x1;
}

extern "C" void kernel_launch(void* const* d_in, const int* in_sizes, int n_in,
                              void* d_out, int out_size) {
    (void)in_sizes; (void)n_in; (void)out_size;
    const float* SE   = (const float*)d_in[0];
    const float* Wa   = (const float*)d_in[1];
    const float* ba   = (const float*)d_in[2];
    const float* g1   = (const float*)d_in[3];
    const float* b1   = (const float*)d_in[4];
    const float* Wp   = (const float*)d_in[5];
    const float* bp   = (const float*)d_in[6];
    const float* g2   = (const float*)d_in[7];
    const float* b2   = (const float*)d_in[8];
    const float* tok  = (const float*)d_in[9];
    const float* Wih0 = (const float*)d_in[10];
    const float* Whh0 = (const float*)d_in[11];
    const float* bih0 = (const float*)d_in[12];
    const float* bhh0 = (const float*)d_in[13];
    const float* Wih1 = (const float*)d_in[14];
    const float* Whh1 = (const float*)d_in[15];
    const float* bih1 = (const float*)d_in[16];
    const float* bhh1 = (const float*)d_in[17];
    const float* Wout = (const float*)d_in[18];
    const float* bout = (const float*)d_in[19];
    const void*  temp = d_in[20];
    float* out = (float*)d_out;

    // Phase A
    k_gemm<<<dim3(Edim/32, Bsz/8), 256>>>(SE, Wa, ba, Edim, Edim, 0);
    k_lnrelu<<<Bsz, 256>>>(g1, b1, Edim, 0);
    k_gemm<<<dim3(Hdim/32, Bsz/8), 256>>>(nullptr, Wp, bp, Edim, Hdim, 1);
    k_lnrelu<<<Bsz, 256>>>(g2, b2, Hdim, 1);
    k_init<<<Bsz, 128>>>(tok, out);
    k_prepW<<<dim3(Vocab/64, Hdim/64), 256>>>(Wout);

    // Phase B: 30 autoregressive steps
    for (int t = 0; t < Steps; t++) {
        uint32_t k0, k1;
        host_threefry(0u, 42u, 0u, (uint32_t)t, k0, k1);
        k_gates<<<dim3(32, 8), 256>>>(Wih0, Whh0, 0);
        k_cell<<<(Bsz*Hdim)/256, 256>>>(bih0, bhh0, 0);
        k_gates<<<dim3(32, 8), 256>>>(Wih1, Whh1, 1);
        k_cell<<<(Bsz*Hdim)/256, 256>>>(bih1, bhh1, 1);
        k_logits_mma<<<Vocab/64, 128>>>(bout, temp, out, t, k0, k1);
        k_final<<<Bsz, 128>>>(tok, out, t);
    }
}